// round 11
// baseline (speedup 1.0000x reference)
#include <cuda_runtime.h>

#define NN 4096
#define FIN 128
#define UNITS 64
#define HEADS 4
#define MAX_E 128          // Binomial(4096,0.01): mean 41, P(deg>128) ~ 1e-20
#define PRE_B 256          // pre blocks (16 rows each)
#define SCAN_B 2048        // scan+agg blocks (2 rows each)
#define DSM_BYTES 15360

__device__ __align__(16) float g_x  [NN * UNITS];
__device__ __align__(16) float g_e1 [NN * HEADS];
__device__ __align__(16) float g_e2 [NN * HEADS];
__device__ __align__(16) float g_S0 [UNITS];
__device__ __align__(16) float g_S0p[PRE_B * UNITS];
__device__ unsigned int g_tickA;   // pre-block completion counter
__device__ unsigned int g_tickB;   // scan-block completion counter (reset duty)
__device__ unsigned int g_ready;   // release flag: pre results visible

// ---------------------------------------------------------------------------
// scan one adjacency row -> smem edge list (deterministic compaction)
// ---------------------------------------------------------------------------
__device__ __forceinline__ void scan_row(const float* __restrict__ arow, int t,
                                         int* __restrict__ ej, int ridx,
                                         int* s_wtot, int* s_woff,
                                         int* s_deg, int* sdegs) {
    float4 v[4];
#pragma unroll
    for (int c = 0; c < 4; c++)
        v[c] = *(const float4*)&arow[c * 1024 + t * 4];
    int cnt = 0;
#pragma unroll
    for (int c = 0; c < 4; c++)
        cnt += (v[c].x != 0.0f) + (v[c].y != 0.0f) +
               (v[c].z != 0.0f) + (v[c].w != 0.0f);

    int lane = t & 31, wid = t >> 5;
    int incl = cnt;
#pragma unroll
    for (int d = 1; d < 32; d <<= 1) {
        int nv = __shfl_up_sync(0xffffffffu, incl, d);
        if (lane >= d) incl += nv;
    }
    if (lane == 31) s_wtot[wid] = incl;
    __syncthreads();
    if (t < 8) {
        int vv = s_wtot[t];
        int inc2 = vv;
#pragma unroll
        for (int d = 1; d < 8; d <<= 1) {
            int nv = __shfl_up_sync(0xffu, inc2, d);
            if (t >= d) inc2 += nv;
        }
        s_woff[t] = inc2 - vv;
        if (t == 7) *s_deg = inc2;
    }
    __syncthreads();

    int off = s_woff[wid] + incl - cnt;
#pragma unroll
    for (int c = 0; c < 4; c++) {
        int jb = c * 1024 + t * 4;
        if (v[c].x != 0.0f) { if (off < MAX_E) ej[off] = jb;     off++; }
        if (v[c].y != 0.0f) { if (off < MAX_E) ej[off] = jb + 1; off++; }
        if (v[c].z != 0.0f) { if (off < MAX_E) ej[off] = jb + 2; off++; }
        if (v[c].w != 0.0f) { if (off < MAX_E) ej[off] = jb + 3; off++; }
    }
    if (t == 0) sdegs[ridx] = min(*s_deg, MAX_E);
}

// ---------------------------------------------------------------------------
// k_all: single fused kernel, heterogeneous grid.
//   bids [0, PRE_B):   pre (x = inp@w, e1/e2, S0) then release g_ready
//   bids [PRE_B, ...): scan 2 adj rows -> smem CSR, acquire g_ready,
//                      softmax-aggregate, write output
// ---------------------------------------------------------------------------
__global__ __launch_bounds__(256) void k_all(const float* __restrict__ adj,
                                             const float* __restrict__ inp,
                                             const float* __restrict__ gw,
                                             const float* __restrict__ aw1,
                                             const float* __restrict__ aw2,
                                             float* __restrict__ out) {
    extern __shared__ __align__(16) char dsm[];
    __shared__ int s_wtot[8], s_woff[8];
    __shared__ int s_deg, s_last, sdegs[2];
    __shared__ float sse[2][HEADS];

    int t = threadIdx.x;

    if (blockIdx.x >= PRE_B) {
        // =============== scan + aggregate (2 rows) ==========================
        int   (*ejs)[MAX_E]         = (int(*)[MAX_E])dsm;                     // 1 KB
        float (*ew)[MAX_E][HEADS]   = (float(*)[MAX_E][HEADS])(dsm + 1024);   // 4 KB
        float (*pacc)[HEADS][UNITS] = (float(*)[HEADS][UNITS])(dsm + 5120);   // 8 KB
        float (*pex)[UNITS]         = (float(*)[UNITS])(dsm + 13312);         // 2 KB

        int i0 = (blockIdx.x - PRE_B) * 2;
        scan_row(adj + (size_t)i0 * NN,       t, ejs[0], 0, s_wtot, s_woff, &s_deg, sdegs);
        __syncthreads();
        scan_row(adj + (size_t)(i0 + 1) * NN, t, ejs[1], 1, s_wtot, s_woff, &s_deg, sdegs);

        // acquire pre results
        if (t == 0) {
            while (*(volatile unsigned int*)&g_ready == 0u) __nanosleep(200);
            __threadfence();
        }
        __syncthreads();

        // phase B: edge weights (one thread per edge slot)
        {
            int r = t >> 7, e = t & 127;
            if (e < sdegs[r]) {
                int j = ejs[r][e];
                float4 e1v = *(const float4*)&g_e1[(i0 + r) * HEADS];
                float4 e2v = *(const float4*)&g_e2[j * HEADS];
                float4 w4;
                w4.x = __expf(fmaxf(e1v.x + e2v.x, 0.0f));
                w4.y = __expf(fmaxf(e1v.y + e2v.y, 0.0f));
                w4.z = __expf(fmaxf(e1v.z + e2v.z, 0.0f));
                w4.w = __expf(fmaxf(e1v.w + e2v.w, 0.0f));
                *(float4*)&ew[r][e][0] = w4;
            }
        }
        __syncthreads();

        // phase C: gather-accumulate. 16 groups x 16 lanes, float4 per lane.
        {
            int g = t >> 4, l = t & 15, u0 = l * 4;
            int r = g >> 3, p = g & 7;
            int deg = sdegs[r];
            float4 A0 = {0,0,0,0}, A1 = {0,0,0,0}, A2 = {0,0,0,0}, A3 = {0,0,0,0};
            float4 EX = {0,0,0,0};
#pragma unroll 2
            for (int e = p; e < deg; e += 8) {
                int j = ejs[r][e];
                float4 xj = *(const float4*)&g_x[(size_t)j * UNITS + u0];
                float4 wv = *(float4*)&ew[r][e][0];
                EX.x += xj.x; EX.y += xj.y; EX.z += xj.z; EX.w += xj.w;
                A0.x += wv.x * xj.x; A0.y += wv.x * xj.y; A0.z += wv.x * xj.z; A0.w += wv.x * xj.w;
                A1.x += wv.y * xj.x; A1.y += wv.y * xj.y; A1.z += wv.y * xj.z; A1.w += wv.y * xj.w;
                A2.x += wv.z * xj.x; A2.y += wv.z * xj.y; A2.z += wv.z * xj.z; A2.w += wv.z * xj.w;
                A3.x += wv.w * xj.x; A3.y += wv.w * xj.y; A3.z += wv.w * xj.z; A3.w += wv.w * xj.w;
            }
            // combine parity pairs: lanes 0-15 absorb lanes 16-31 (same row)
#define PRED4(V) { V.x += __shfl_down_sync(0xffffffffu, V.x, 16); \
                   V.y += __shfl_down_sync(0xffffffffu, V.y, 16); \
                   V.z += __shfl_down_sync(0xffffffffu, V.z, 16); \
                   V.w += __shfl_down_sync(0xffffffffu, V.w, 16); }
            PRED4(A0) PRED4(A1) PRED4(A2) PRED4(A3) PRED4(EX)
#undef PRED4
            if (l == (t & 31)) {   // lanes 0-15 of each warp
                int w = t >> 5;    // 8 warp-partials: warps 0-3 row0, 4-7 row1
                *(float4*)&pacc[w][0][u0] = A0;
                *(float4*)&pacc[w][1][u0] = A1;
                *(float4*)&pacc[w][2][u0] = A2;
                *(float4*)&pacc[w][3][u0] = A3;
                *(float4*)&pex[w][u0] = EX;
            }
        }
        __syncthreads();

        if (t < 64) {   // per-row per-head exp-sums
            int r = t >> 5, lane = t & 31;
            int h = lane & 3, es = lane >> 2;
            int deg = sdegs[r];
            float s = 0.0f;
            for (int e = es; e < deg; e += 8) s += ew[r][e][h];
#pragma unroll
            for (int d = 16; d >= 4; d >>= 1)
                s += __shfl_down_sync(0xffffffffu, s, d);
            if (lane < 4) sse[r][h] = s;
        }
        __syncthreads();

        // finalize: 512 outputs, 2 per thread
#pragma unroll
        for (int k = 0; k < 2; k++) {
            int o = t + k * 256;
            int r = o >> 8, h = (o >> 6) & 3, u = o & 63;
            int w0 = r * 4;
            float A  = pacc[w0][h][u] + pacc[w0 + 1][h][u] +
                       pacc[w0 + 2][h][u] + pacc[w0 + 3][h][u];
            float Ex = pex[w0][u] + pex[w0 + 1][u] + pex[w0 + 2][u] + pex[w0 + 3][u];
            float Z  = (float)(NN - sdegs[r]) + sse[r][h];
            float val = (g_S0[u] - Ex + A) / Z;
            out[(size_t)(i0 + r) * (HEADS * UNITS) + (o & 255)] = fmaxf(val, 0.0f);
        }

        // reset duty: last scan block clears flags for the next graph replay
        __syncthreads();
        if (t == 0) {
            unsigned int v = atomicAdd(&g_tickB, 1u);
            if (v == SCAN_B - 1) {
                *(volatile unsigned int*)&g_ready = 0u;
                g_tickB = 0u;
            }
        }
        return;
    }

    // =============== pre: 16 rows (x, e1/e2, S0) ============================
    float (*is)[132]          = (float(*)[132])dsm;                        // 8.25 KB
    float (*xs)[68]           = (float(*)[68])(dsm + 8448);                // 4.25 KB
    float (*awd)[UNITS][HEADS] = (float(*)[UNITS][HEADS])(dsm + 12800);    // 2 KB

    int b  = blockIdx.x;
    int r0 = b * 16;

    {   // stage inp tile (16 x 128) + attn weights
        const float4* gi = (const float4*)(inp + (size_t)r0 * FIN);
#pragma unroll
        for (int i = 0; i < 2; i++) {
            int f = t + 256 * i;
            *(float4*)&is[f >> 5][(f & 31) * 4] = gi[f];
        }
        if (t < 64)       *(float4*)&awd[0][t][0]      = ((const float4*)aw1)[t];
        else if (t < 128) *(float4*)&awd[1][t - 64][0] = ((const float4*)aw2)[t - 64];
    }
    __syncthreads();

    {   // GEMM: warp -> 2 rows, lane -> 2 cols.  w through L1 (32 KB, hot).
        int wd = t >> 5, lane = t & 31;
        int ra = wd * 2, c = lane * 2;
        float a00 = 0, a01 = 0, a10 = 0, a11 = 0;
#pragma unroll 8
        for (int k = 0; k < FIN; k++) {
            float2 wv = __ldg((const float2*)&gw[k * UNITS + c]);
            float  i0 = is[ra][k];
            float  i1 = is[ra + 1][k];
            a00 += i0 * wv.x; a01 += i0 * wv.y;
            a10 += i1 * wv.x; a11 += i1 * wv.y;
        }
        float2 o0 = make_float2(a00, a01);
        float2 o1 = make_float2(a10, a11);
        *(float2*)&g_x[(size_t)(r0 + ra)     * UNITS + c] = o0;
        *(float2*)&g_x[(size_t)(r0 + ra + 1) * UNITS + c] = o1;
        *(float2*)&xs[ra][c]     = o0;
        *(float2*)&xs[ra + 1][c] = o1;
    }
    __syncthreads();

    if (t < 128) {   // e1/e2: (row = t>>3, m = (t>>2)&1, h = t&3)
        int row = t >> 3, m = (t >> 2) & 1, h = t & 3;
        float e = 0.0f;
#pragma unroll 16
        for (int u = 0; u < UNITS; u++) e += xs[row][u] * awd[m][u][h];
        if (m) g_e2[(r0 + row) * HEADS + h] = e;
        else   g_e1[(r0 + row) * HEADS + h] = e;
    } else if (t < 192) {   // colsum partial
        int u = t - 128;
        float s = 0.0f;
#pragma unroll
        for (int r = 0; r < 16; r++) s += xs[r][u];
        g_S0p[b * UNITS + u] = s;
    }
    __syncthreads();

    if (t == 0) {
        __threadfence();
        s_last = (atomicAdd(&g_tickA, 1u) == PRE_B - 1);
    }
    __syncthreads();
    if (s_last) {   // final S0 reduce, then release
        float* red = (float*)xs;
        int u = t & 63, q = t >> 6;
        float s = 0.0f;
#pragma unroll 4
        for (int bb = q; bb < PRE_B; bb += 4) s += g_S0p[bb * UNITS + u];
        red[q * UNITS + u] = s;
        __syncthreads();
        if (t < UNITS)
            g_S0[t] = red[t] + red[UNITS + t] + red[2 * UNITS + t] + red[3 * UNITS + t];
        __syncthreads();
        if (t == 0) {
            g_tickA = 0u;
            __threadfence();
            *(volatile unsigned int*)&g_ready = 1u;   // release
        }
    }
}

// ---------------------------------------------------------------------------
extern "C" void kernel_launch(void* const* d_in, const int* in_sizes, int n_in,
                              void* d_out, int out_size) {
    const float* inp = (const float*)d_in[0];
    const float* adj = (const float*)d_in[1];
    const float* w   = (const float*)d_in[2];
    const float* aw1 = (const float*)d_in[3];
    const float* aw2 = (const float*)d_in[4];
    float* out = (float*)d_out;

    k_all<<<PRE_B + SCAN_B, 256, DSM_BYTES>>>(adj, inp, w, aw1, aw2, out);
}

// round 13
// speedup vs baseline: 1.1220x; 1.1220x over previous
#include <cuda_runtime.h>

#define NN 4096
#define FIN 128
#define UNITS 64
#define HEADS 4
#define MAX_E 128          // Binomial(4096,0.01): mean 41, P(deg>128) ~ 1e-20
#define PRE_B 256          // pre-lite blocks (16 rows each)
#define SCAN_B 2048        // scan blocks (2 rows each)

__device__ __align__(16) float g_x  [NN * UNITS];
__device__ __align__(16) float g_e1 [NN * HEADS];
__device__ __align__(16) float g_e2 [NN * HEADS];
__device__ __align__(16) float g_S0 [UNITS];
__device__ __align__(16) float g_S0p[PRE_B * UNITS];
__device__ __align__(16) int   g_deg[NN];
__device__ __align__(16) int   g_ej [NN * MAX_E];
__device__ unsigned int g_ticket;

// ---------------------------------------------------------------------------
// k_main: heterogeneous grid.
//   blocks [0, PRE_B):            pre-lite (x = inp@w, e1/e2, S0) — w via L1
//   blocks [PRE_B, PRE_B+SCAN_B): scan 2 adjacency rows -> CSR, dual prefetch
// ---------------------------------------------------------------------------
__global__ __launch_bounds__(256) void k_main(const float* __restrict__ adj,
                                              const float* __restrict__ inp,
                                              const float* __restrict__ gw,
                                              const float* __restrict__ aw1,
                                              const float* __restrict__ aw2) {
    __shared__ __align__(16) float is[16][132];            // 8.25 KB inp tile
    __shared__ __align__(16) float xs[16][68];             // 4.25 KB x tile / S0 reduce
    __shared__ __align__(16) float awd[2][UNITS][HEADS];   // 2 KB
    __shared__ __align__(16) int   s_wtot[2][8];
    __shared__ __align__(16) int   s_woff[2][8];
    __shared__ int s_deg2[2], s_last;

    int t = threadIdx.x;

    if (blockIdx.x >= PRE_B) {
        // ---------------- scan: 2 rows, dual-prefetch ----------------------
        int i0 = (blockIdx.x - PRE_B) * 2;
        const float* a0 = adj + (size_t)i0 * NN;
        const float* a1 = a0 + NN;

        float4 v0[4], v1[4];
#pragma unroll
        for (int c = 0; c < 4; c++) v0[c] = *(const float4*)&a0[c * 1024 + t * 4];
#pragma unroll
        for (int c = 0; c < 4; c++) v1[c] = *(const float4*)&a1[c * 1024 + t * 4];

        int cnt0 = 0, cnt1 = 0;
#pragma unroll
        for (int c = 0; c < 4; c++) {
            cnt0 += (v0[c].x != 0.0f) + (v0[c].y != 0.0f) +
                    (v0[c].z != 0.0f) + (v0[c].w != 0.0f);
            cnt1 += (v1[c].x != 0.0f) + (v1[c].y != 0.0f) +
                    (v1[c].z != 0.0f) + (v1[c].w != 0.0f);
        }

        int lane = t & 31, wid = t >> 5;
        int in0 = cnt0, in1 = cnt1;
#pragma unroll
        for (int d = 1; d < 32; d <<= 1) {
            int n0 = __shfl_up_sync(0xffffffffu, in0, d);
            int n1 = __shfl_up_sync(0xffffffffu, in1, d);
            if (lane >= d) { in0 += n0; in1 += n1; }
        }
        if (lane == 31) { s_wtot[0][wid] = in0; s_wtot[1][wid] = in1; }
        __syncthreads();
        if (t < 16) {   // both block-level prefix sums, width-8 groups
            int r = t >> 3, k = t & 7;
            int vv = s_wtot[r][k];
            int inc = vv;
#pragma unroll
            for (int d = 1; d < 8; d <<= 1) {
                int nv = __shfl_up_sync(0xffffu, inc, d, 8);
                if (k >= d) inc += nv;
            }
            s_woff[r][k] = inc - vv;
            if (k == 7) s_deg2[r] = inc;
        }
        __syncthreads();

        {   // write row0 edge list
            int off = s_woff[0][wid] + in0 - cnt0;
            int* ej = g_ej + i0 * MAX_E;
#pragma unroll
            for (int c = 0; c < 4; c++) {
                int jb = c * 1024 + t * 4;
                if (v0[c].x != 0.0f) { if (off < MAX_E) ej[off] = jb;     off++; }
                if (v0[c].y != 0.0f) { if (off < MAX_E) ej[off] = jb + 1; off++; }
                if (v0[c].z != 0.0f) { if (off < MAX_E) ej[off] = jb + 2; off++; }
                if (v0[c].w != 0.0f) { if (off < MAX_E) ej[off] = jb + 3; off++; }
            }
        }
        {   // write row1 edge list
            int off = s_woff[1][wid] + in1 - cnt1;
            int* ej = g_ej + (i0 + 1) * MAX_E;
#pragma unroll
            for (int c = 0; c < 4; c++) {
                int jb = c * 1024 + t * 4;
                if (v1[c].x != 0.0f) { if (off < MAX_E) ej[off] = jb;     off++; }
                if (v1[c].y != 0.0f) { if (off < MAX_E) ej[off] = jb + 1; off++; }
                if (v1[c].z != 0.0f) { if (off < MAX_E) ej[off] = jb + 2; off++; }
                if (v1[c].w != 0.0f) { if (off < MAX_E) ej[off] = jb + 3; off++; }
            }
        }
        if (t == 0) {
            g_deg[i0]     = min(s_deg2[0], MAX_E);
            g_deg[i0 + 1] = min(s_deg2[1], MAX_E);
        }
        return;
    }

    // ---------------- pre-lite: 16 rows ------------------------------------
    int b  = blockIdx.x;
    int r0 = b * 16;

    {   // stage inp tile (16 x 128) + attn weights
        const float4* gi = (const float4*)(inp + (size_t)r0 * FIN);
#pragma unroll
        for (int i = 0; i < 2; i++) {
            int f = t + 256 * i;
            *(float4*)&is[f >> 5][(f & 31) * 4] = gi[f];
        }
        if (t < 64)       *(float4*)&awd[0][t][0]      = ((const float4*)aw1)[t];
        else if (t < 128) *(float4*)&awd[1][t - 64][0] = ((const float4*)aw2)[t - 64];
    }
    __syncthreads();

    {   // GEMM: warp -> 2 rows, lane -> 2 cols.  w through L1 (32 KB, hot).
        int wd = t >> 5, lane = t & 31;
        int ra = wd * 2, c = lane * 2;
        float a00 = 0, a01 = 0, a10 = 0, a11 = 0;
#pragma unroll 8
        for (int k = 0; k < FIN; k++) {
            float2 wv = __ldg((const float2*)&gw[k * UNITS + c]);
            float  i0 = is[ra][k];
            float  i1 = is[ra + 1][k];
            a00 += i0 * wv.x; a01 += i0 * wv.y;
            a10 += i1 * wv.x; a11 += i1 * wv.y;
        }
        float2 o0 = make_float2(a00, a01);
        float2 o1 = make_float2(a10, a11);
        *(float2*)&g_x[(size_t)(r0 + ra)     * UNITS + c] = o0;
        *(float2*)&g_x[(size_t)(r0 + ra + 1) * UNITS + c] = o1;
        *(float2*)&xs[ra][c]     = o0;
        *(float2*)&xs[ra + 1][c] = o1;
    }
    __syncthreads();

    if (t < 128) {   // e1/e2: (row = t>>3, m = (t>>2)&1, h = t&3)
        int row = t >> 3, m = (t >> 2) & 1, h = t & 3;
        float e = 0.0f;
#pragma unroll 16
        for (int u = 0; u < UNITS; u++) e += xs[row][u] * awd[m][u][h];
        if (m) g_e2[(r0 + row) * HEADS + h] = e;
        else   g_e1[(r0 + row) * HEADS + h] = e;
    } else if (t < 192) {   // colsum partial
        int u = t - 128;
        float s = 0.0f;
#pragma unroll
        for (int r = 0; r < 16; r++) s += xs[r][u];
        g_S0p[b * UNITS + u] = s;
    }
    __syncthreads();

    if (t == 0) {
        __threadfence();
        s_last = (atomicAdd(&g_ticket, 1u) == PRE_B - 1);
    }
    __syncthreads();
    if (s_last) {   // deterministic final S0 reduce
        float* red = (float*)xs;
        int u = t & 63, q = t >> 6;
        float s = 0.0f;
#pragma unroll 4
        for (int bb = q; bb < PRE_B; bb += 4) s += g_S0p[bb * UNITS + u];
        red[q * UNITS + u] = s;
        __syncthreads();
        if (t < UNITS)
            g_S0[t] = red[t] + red[UNITS + t] + red[2 * UNITS + t] + red[3 * UNITS + t];
        if (t == 64) g_ticket = 0u;
    }
}

// ---------------------------------------------------------------------------
// k_agg: softmax-aggregate, 2 rows per block (grid 2048, 256 thr).
// Phase C: 16 groups x 16 lanes, float4 gathers (LDG.128), warp shfl merge.
// ---------------------------------------------------------------------------
__global__ __launch_bounds__(256) void k_agg(float* __restrict__ out) {
    __shared__ __align__(16) int    ejs[2][MAX_E];                // 1 KB
    __shared__ __align__(16) float  ew[2][MAX_E][HEADS];          // 4 KB
    __shared__ __align__(16) float  pacc[8][HEADS][UNITS];        // 8 KB (warp partials)
    __shared__ __align__(16) float  pex[8][UNITS];                // 2 KB
    __shared__ __align__(16) float  sse[2][HEADS];
    __shared__ __align__(16) float4 s_e1[2];
    __shared__ int s_deg[2];

    int t  = threadIdx.x;
    int i0 = blockIdx.x * 2;

    {   // phase A: unconditional CSR load (1 edge slot per thread) + scalars
        int r = t >> 7, e = t & 127;
        ejs[r][e] = g_ej[(i0 + r) * MAX_E + e];
        if (t < 2)  s_deg[t] = g_deg[i0 + t];
        if (t >= 254) s_e1[t - 254] = *(const float4*)&g_e1[(i0 + t - 254) * HEADS];
    }
    __syncthreads();

    {   // phase B: edge weights (one thread per edge slot)
        int r = t >> 7, e = t & 127;
        if (e < s_deg[r]) {
            int j = ejs[r][e];
            float4 e1v = s_e1[r];
            float4 e2v = *(const float4*)&g_e2[j * HEADS];
            float4 w4;
            w4.x = __expf(fmaxf(e1v.x + e2v.x, 0.0f));
            w4.y = __expf(fmaxf(e1v.y + e2v.y, 0.0f));
            w4.z = __expf(fmaxf(e1v.z + e2v.z, 0.0f));
            w4.w = __expf(fmaxf(e1v.w + e2v.w, 0.0f));
            *(float4*)&ew[r][e][0] = w4;
        }
    }
    __syncthreads();

    {   // phase C: gather-accumulate. 16 groups x 16 lanes, float4 per lane.
        int g = t >> 4, l = t & 15, u0 = l * 4;
        int r = g >> 3, p = g & 7;
        int deg = s_deg[r];
        float4 A0 = {0,0,0,0}, A1 = {0,0,0,0}, A2 = {0,0,0,0}, A3 = {0,0,0,0};
        float4 EX = {0,0,0,0};
#pragma unroll 2
        for (int e = p; e < deg; e += 8) {
            int j = ejs[r][e];
            float4 xj = *(const float4*)&g_x[(size_t)j * UNITS + u0];
            float4 wv = *(float4*)&ew[r][e][0];
            EX.x += xj.x; EX.y += xj.y; EX.z += xj.z; EX.w += xj.w;
            A0.x += wv.x * xj.x; A0.y += wv.x * xj.y; A0.z += wv.x * xj.z; A0.w += wv.x * xj.w;
            A1.x += wv.y * xj.x; A1.y += wv.y * xj.y; A1.z += wv.y * xj.z; A1.w += wv.y * xj.w;
            A2.x += wv.z * xj.x; A2.y += wv.z * xj.y; A2.z += wv.z * xj.z; A2.w += wv.z * xj.w;
            A3.x += wv.w * xj.x; A3.y += wv.w * xj.y; A3.z += wv.w * xj.z; A3.w += wv.w * xj.w;
        }
        // merge the two edge-parities living in one warp (lanes 0-15 absorb 16-31)
#define PRED4(V) { V.x += __shfl_down_sync(0xffffffffu, V.x, 16); \
                   V.y += __shfl_down_sync(0xffffffffu, V.y, 16); \
                   V.z += __shfl_down_sync(0xffffffffu, V.z, 16); \
                   V.w += __shfl_down_sync(0xffffffffu, V.w, 16); }
        PRED4(A0) PRED4(A1) PRED4(A2) PRED4(A3) PRED4(EX)
#undef PRED4
        if ((t & 31) < 16) {   // lanes 0-15 hold warp partial
            int w = t >> 5;    // warps 0-3 -> row0, warps 4-7 -> row1
            *(float4*)&pacc[w][0][u0] = A0;
            *(float4*)&pacc[w][1][u0] = A1;
            *(float4*)&pacc[w][2][u0] = A2;
            *(float4*)&pacc[w][3][u0] = A3;
            *(float4*)&pex[w][u0] = EX;
        }
    }
    __syncthreads();

    if (t < 64) {   // per-row per-head exp-sums
        int r = t >> 5, lane = t & 31;
        int h = lane & 3, es = lane >> 2;
        int deg = s_deg[r];
        float s = 0.0f;
        for (int e = es; e < deg; e += 8) s += ew[r][e][h];
#pragma unroll
        for (int d = 16; d >= 4; d >>= 1)
            s += __shfl_down_sync(0xffffffffu, s, d);
        if (lane < 4) sse[r][h] = s;
    }
    __syncthreads();

    // finalize: 512 outputs, 2 per thread
#pragma unroll
    for (int k = 0; k < 2; k++) {
        int o = t + k * 256;
        int r = o >> 8, h = (o >> 6) & 3, u = o & 63;
        int w0 = r * 4;
        float A  = pacc[w0][h][u] + pacc[w0 + 1][h][u] +
                   pacc[w0 + 2][h][u] + pacc[w0 + 3][h][u];
        float Ex = pex[w0][u] + pex[w0 + 1][u] + pex[w0 + 2][u] + pex[w0 + 3][u];
        float Z  = (float)(NN - s_deg[r]) + sse[r][h];
        float val = (g_S0[u] - Ex + A) / Z;
        out[(size_t)(i0 + r) * (HEADS * UNITS) + (o & 255)] = fmaxf(val, 0.0f);
    }
}

// ---------------------------------------------------------------------------
extern "C" void kernel_launch(void* const* d_in, const int* in_sizes, int n_in,
                              void* d_out, int out_size) {
    const float* inp = (const float*)d_in[0];
    const float* adj = (const float*)d_in[1];
    const float* w   = (const float*)d_in[2];
    const float* aw1 = (const float*)d_in[3];
    const float* aw2 = (const float*)d_in[4];
    float* out = (float*)d_out;

    k_main<<<PRE_B + SCAN_B, 256>>>(adj, inp, w, aw1, aw2);
    k_agg <<<NN / 2, 256>>>(out);
}